// round 1
// baseline (speedup 1.0000x reference)
#include <cuda_runtime.h>
#include <cuda_bf16.h>

#define D 64
#define NMAX 100000
#define EMAX 1000000

// Scratch (allocation-free rule: __device__ globals)
__device__ float g_deg_out[NMAX];            // out-degree -> rsqrt in place
__device__ float g_deg_in[NMAX];             // in-degree  -> rsqrt in place
__device__ float g_agg[(size_t)NMAX * D];    // scatter accumulator
__device__ float g_h1[(size_t)NMAX * D];     // layer-1 output

// ---------------------------------------------------------------------------
// Degree counting
// ---------------------------------------------------------------------------
__global__ void k_deg(const int* __restrict__ src, const int* __restrict__ dst, int E) {
    int e = blockIdx.x * blockDim.x + threadIdx.x;
    if (e < E) {
        atomicAdd(&g_deg_out[src[e]], 1.0f);
        atomicAdd(&g_deg_in[dst[e]], 1.0f);
    }
}

__global__ void k_isqrt(int N) {
    int i = blockIdx.x * blockDim.x + threadIdx.x;
    if (i < N) {
        g_deg_out[i] = rsqrtf(fmaxf(g_deg_out[i], 1.0f));
        g_deg_in[i]  = rsqrtf(fmaxf(g_deg_in[i], 1.0f));
    }
}

// ---------------------------------------------------------------------------
// Gather + scale + scatter-add. 16 threads per edge, each owning one float4
// chunk of the 64-wide feature row. red.global.add.v4.f32 -> 16 reds/edge.
// ---------------------------------------------------------------------------
__global__ void k_scatter(const float* __restrict__ x,
                          const int* __restrict__ src,
                          const int* __restrict__ dst, int E) {
    int gid = blockIdx.x * blockDim.x + threadIdx.x;
    int e = gid >> 4;
    if (e >= E) return;
    int c = (gid & 15) << 2;                 // float column offset (multiple of 4)
    int s = src[e];
    int d = dst[e];
    float sc = g_deg_out[s];                 // rsqrt(out_deg(src))
    float4 v = *reinterpret_cast<const float4*>(x + (size_t)s * D + c);
    v.x *= sc; v.y *= sc; v.z *= sc; v.w *= sc;
    float* p = g_agg + (size_t)d * D + c;
    asm volatile("red.global.add.v4.f32 [%0], {%1,%2,%3,%4};"
                 :: "l"(p), "f"(v.x), "f"(v.y), "f"(v.z), "f"(v.w) : "memory");
}

// ---------------------------------------------------------------------------
// Per-node 64x64 GEMM: out = leaky_relu((agg * in_isqrt) @ W + b)
// 64 nodes / block, 256 threads, 4 threads per node (16 output cols each).
// FUSE: additionally computes the 64->2 classifier and writes [N,2] output.
// ---------------------------------------------------------------------------
template <bool FUSE>
__global__ void k_gemm(const float* __restrict__ in,
                       const float* __restrict__ W,
                       const float* __restrict__ b,
                       const float* __restrict__ Wc,
                       const float* __restrict__ bc,
                       float* __restrict__ out, int N) {
    __shared__ float sW[D * D];        // 16 KB
    __shared__ float sX[64][D + 4];    // padded rows: conflict-free sX[n][k]
    __shared__ float sWc[D * 2];

    int tid = threadIdx.x;
    int nb = blockIdx.x * 64;

    for (int i = tid; i < D * D; i += 256) sW[i] = W[i];
    if (FUSE && tid < D * 2) sWc[tid] = Wc[tid];

    // stage X, scaled by rsqrt(in_deg) (coalesced global reads)
    for (int i = tid; i < 64 * D; i += 256) {
        int n = i >> 6, k = i & 63;
        int node = nb + n;
        float v = 0.0f;
        if (node < N) v = in[(size_t)node * D + k] * g_deg_in[node];
        sX[n][k] = v;
    }
    __syncthreads();

    int n = tid >> 2;          // local node
    int q = tid & 3;           // column quarter
    int node = nb + n;

    float acc[16];
#pragma unroll
    for (int j = 0; j < 16; j++) acc[j] = b[q * 16 + j];

#pragma unroll 4
    for (int k = 0; k < D; k++) {
        float a = sX[n][k];
        const float4* wr = reinterpret_cast<const float4*>(&sW[k * D + q * 16]);
#pragma unroll
        for (int j4 = 0; j4 < 4; j4++) {
            float4 w = wr[j4];
            acc[j4 * 4 + 0] = fmaf(a, w.x, acc[j4 * 4 + 0]);
            acc[j4 * 4 + 1] = fmaf(a, w.y, acc[j4 * 4 + 1]);
            acc[j4 * 4 + 2] = fmaf(a, w.z, acc[j4 * 4 + 2]);
            acc[j4 * 4 + 3] = fmaf(a, w.w, acc[j4 * 4 + 3]);
        }
    }

#pragma unroll
    for (int j = 0; j < 16; j++) {
        float v = acc[j];
        acc[j] = v > 0.0f ? v : 0.01f * v;   // leaky_relu
    }

    if (!FUSE) {
        if (node < N) {
            float4* o = reinterpret_cast<float4*>(out + (size_t)node * D + q * 16);
#pragma unroll
            for (int j4 = 0; j4 < 4; j4++)
                o[j4] = make_float4(acc[j4 * 4], acc[j4 * 4 + 1],
                                    acc[j4 * 4 + 2], acc[j4 * 4 + 3]);
        }
    } else {
        // fused 64->2 classifier: partial dot per quarter, shfl-reduce over 4 lanes
        float p0 = 0.0f, p1 = 0.0f;
#pragma unroll
        for (int j = 0; j < 16; j++) {
            int f = q * 16 + j;
            p0 = fmaf(acc[j], sWc[f * 2 + 0], p0);
            p1 = fmaf(acc[j], sWc[f * 2 + 1], p1);
        }
        p0 += __shfl_down_sync(0xffffffffu, p0, 2);
        p1 += __shfl_down_sync(0xffffffffu, p1, 2);
        p0 += __shfl_down_sync(0xffffffffu, p0, 1);
        p1 += __shfl_down_sync(0xffffffffu, p1, 1);
        if (q == 0 && node < N) {
            out[(size_t)node * 2 + 0] = p0 + bc[0];
            out[(size_t)node * 2 + 1] = p1 + bc[1];
        }
    }
}

// ---------------------------------------------------------------------------
extern "C" void kernel_launch(void* const* d_in, const int* in_sizes, int n_in,
                              void* d_out, int out_size) {
    const float* x  = (const float*)d_in[0];
    const int*   src = (const int*)d_in[1];
    const int*   dst = (const int*)d_in[2];
    const float* W1 = (const float*)d_in[3];
    const float* b1 = (const float*)d_in[4];
    const float* W2 = (const float*)d_in[5];
    const float* b2 = (const float*)d_in[6];
    const float* Wc = (const float*)d_in[7];
    const float* bc = (const float*)d_in[8];
    float* out = (float*)d_out;

    int N = in_sizes[0] / D;
    int E = in_sizes[1];

    void *p_deg_out, *p_deg_in, *p_agg, *p_h1;
    cudaGetSymbolAddress(&p_deg_out, g_deg_out);
    cudaGetSymbolAddress(&p_deg_in,  g_deg_in);
    cudaGetSymbolAddress(&p_agg,     g_agg);
    cudaGetSymbolAddress(&p_h1,      g_h1);

    // degrees
    cudaMemsetAsync(p_deg_out, 0, (size_t)N * sizeof(float), 0);
    cudaMemsetAsync(p_deg_in,  0, (size_t)N * sizeof(float), 0);
    k_deg<<<(E + 255) / 256, 256>>>(src, dst, E);
    k_isqrt<<<(N + 255) / 256, 256>>>(N);

    int sblk = (E * 16 + 255) / 256;
    int gblk = (N + 63) / 64;

    // layer 1
    cudaMemsetAsync(p_agg, 0, (size_t)N * D * sizeof(float), 0);
    k_scatter<<<sblk, 256>>>(x, src, dst, E);
    k_gemm<false><<<gblk, 256>>>((const float*)p_agg, W1, b1, nullptr, nullptr,
                                 (float*)p_h1, N);

    // layer 2 + fused classifier
    cudaMemsetAsync(p_agg, 0, (size_t)N * D * sizeof(float), 0);
    k_scatter<<<sblk, 256>>>((const float*)p_h1, src, dst, E);
    k_gemm<true><<<gblk, 256>>>((const float*)p_agg, W2, b2, Wc, bc, out, N);
}

// round 2
// speedup vs baseline: 1.5321x; 1.5321x over previous
#include <cuda_runtime.h>
#include <cuda_bf16.h>

#define D 64
#define NMAX 100000
#define EMAX 1000000

// Scratch (allocation-free rule: __device__ globals)
__device__ float g_deg_out[NMAX];            // out-degree -> rsqrt in place
__device__ float g_deg_in[NMAX];             // in-degree  -> rsqrt in place
__device__ float g_agg[(size_t)NMAX * D];    // scatter accumulator
__device__ float g_h1[(size_t)NMAX * D];     // layer-1 output

// ---------------------------------------------------------------------------
// packed f32x2 helpers (Blackwell FFMA2 — only reachable via PTX)
// ---------------------------------------------------------------------------
__device__ __forceinline__ unsigned long long pack2(float lo, float hi) {
    unsigned long long r;
    asm("mov.b64 %0, {%1, %2};" : "=l"(r) : "f"(lo), "f"(hi));
    return r;
}
__device__ __forceinline__ void unpack2(unsigned long long v, float& lo, float& hi) {
    asm("mov.b64 {%0, %1}, %2;" : "=f"(lo), "=f"(hi) : "l"(v));
}
__device__ __forceinline__ unsigned long long fma2(unsigned long long a,
                                                   unsigned long long b,
                                                   unsigned long long c) {
    unsigned long long d;
    asm("fma.rn.f32x2 %0, %1, %2, %3;" : "=l"(d) : "l"(a), "l"(b), "l"(c));
    return d;
}

// ---------------------------------------------------------------------------
// Degree counting
// ---------------------------------------------------------------------------
__global__ void k_deg(const int* __restrict__ src, const int* __restrict__ dst, int E) {
    int e = blockIdx.x * blockDim.x + threadIdx.x;
    if (e < E) {
        atomicAdd(&g_deg_out[src[e]], 1.0f);
        atomicAdd(&g_deg_in[dst[e]], 1.0f);
    }
}

__global__ void k_isqrt(int N) {
    int i = blockIdx.x * blockDim.x + threadIdx.x;
    if (i < N) {
        g_deg_out[i] = rsqrtf(fmaxf(g_deg_out[i], 1.0f));
        g_deg_in[i]  = rsqrtf(fmaxf(g_deg_in[i], 1.0f));
    }
}

// ---------------------------------------------------------------------------
// Gather + scale + scatter-add. 16 threads per edge, each owning one float4
// chunk of the 64-wide feature row. red.global.add.v4.f32 -> 16 reds/edge.
// ---------------------------------------------------------------------------
__global__ void k_scatter(const float* __restrict__ x,
                          const int* __restrict__ src,
                          const int* __restrict__ dst, int E) {
    int gid = blockIdx.x * blockDim.x + threadIdx.x;
    int e = gid >> 4;
    if (e >= E) return;
    int c = (gid & 15) << 2;                 // float column offset (multiple of 4)
    int s = src[e];
    int d = dst[e];
    float sc = g_deg_out[s];                 // rsqrt(out_deg(src))
    float4 v = *reinterpret_cast<const float4*>(x + (size_t)s * D + c);
    v.x *= sc; v.y *= sc; v.z *= sc; v.w *= sc;
    float* p = g_agg + (size_t)d * D + c;
    asm volatile("red.global.add.v4.f32 [%0], {%1,%2,%3,%4};"
                 :: "l"(p), "f"(v.x), "f"(v.y), "f"(v.z), "f"(v.w) : "memory");
}

// ---------------------------------------------------------------------------
// Register-tiled node GEMM: out = leaky_relu((agg * in_isqrt) @ W + b)
// 128 nodes / block, 128 threads. Thread = (node-group g = tid>>2) x
// (col-quarter q = tid&3); computes 4 nodes x 16 cols via packed f32x2 FMA.
// FUSE: additionally computes the 64->2 classifier and writes [N,2] output.
// ---------------------------------------------------------------------------
#define XPAD 65

template <bool FUSE>
__global__ __launch_bounds__(128) void k_gemm(const float* __restrict__ in,
                       const float* __restrict__ W,
                       const float* __restrict__ b,
                       const float* __restrict__ Wc,
                       const float* __restrict__ bc,
                       float* __restrict__ out, int N) {
    extern __shared__ float smem[];
    float* sW = smem;                        // D*D = 4096 floats
    float* sX = sW + D * D;                  // 128 * XPAD floats
    float* sWc = sX + 128 * XPAD;            // D*2 floats

    int tid = threadIdx.x;
    int nb = blockIdx.x * 128;

    for (int i = tid; i < D * D; i += 128) sW[i] = W[i];
    if (FUSE) sWc[tid] = Wc[tid];            // exactly 128 entries

    // stage X, scaled by rsqrt(in_deg) (coalesced reads, conflict-free writes)
    for (int i = tid; i < 128 * D; i += 128) {
        int n = i >> 6, k = i & 63;
        int node = nb + n;
        float v = 0.0f;
        if (node < N) v = in[(size_t)node * D + k] * g_deg_in[node];
        sX[n * XPAD + k] = v;
    }
    __syncthreads();

    int q = tid & 3;                         // column quarter (16 cols)
    int g = tid >> 2;                        // node group
    int n0 = g * 4;

    // accumulators: 4 nodes x 8 f32x2 pairs (= 16 cols)
    unsigned long long acc[4][8];
    {
        unsigned long long binit[8];
#pragma unroll
        for (int j = 0; j < 8; j++) binit[j] = pack2(b[q * 16 + 2 * j], b[q * 16 + 2 * j + 1]);
#pragma unroll
        for (int m = 0; m < 4; m++)
#pragma unroll
            for (int j = 0; j < 8; j++) acc[m][j] = binit[j];
    }

    unsigned wbase = (unsigned)__cvta_generic_to_shared(&sW[q * 16]);
    unsigned xbase = (unsigned)__cvta_generic_to_shared(&sX[n0 * XPAD]);

#pragma unroll 4
    for (int k = 0; k < D; k++) {
        unsigned long long w2[8];
        unsigned waddr = wbase + k * (D * 4);
        asm("ld.shared.v2.u64 {%0,%1}, [%2];" : "=l"(w2[0]), "=l"(w2[1]) : "r"(waddr));
        asm("ld.shared.v2.u64 {%0,%1}, [%2];" : "=l"(w2[2]), "=l"(w2[3]) : "r"(waddr + 16));
        asm("ld.shared.v2.u64 {%0,%1}, [%2];" : "=l"(w2[4]), "=l"(w2[5]) : "r"(waddr + 32));
        asm("ld.shared.v2.u64 {%0,%1}, [%2];" : "=l"(w2[6]), "=l"(w2[7]) : "r"(waddr + 48));
#pragma unroll
        for (int m = 0; m < 4; m++) {
            float a;
            asm("ld.shared.f32 %0, [%1];" : "=f"(a)
                : "r"(xbase + (m * XPAD + k) * 4));
            unsigned long long a2 = pack2(a, a);
#pragma unroll
            for (int j = 0; j < 8; j++) acc[m][j] = fma2(a2, w2[j], acc[m][j]);
        }
    }

#pragma unroll
    for (int m = 0; m < 4; m++) {
        int node = nb + n0 + m;
        float v[16];
#pragma unroll
        for (int j = 0; j < 8; j++) unpack2(acc[m][j], v[2 * j], v[2 * j + 1]);
#pragma unroll
        for (int j = 0; j < 16; j++) v[j] = v[j] > 0.0f ? v[j] : 0.01f * v[j];

        if (!FUSE) {
            if (node < N) {
                float4* o = reinterpret_cast<float4*>(out + (size_t)node * D + q * 16);
                o[0] = make_float4(v[0], v[1], v[2], v[3]);
                o[1] = make_float4(v[4], v[5], v[6], v[7]);
                o[2] = make_float4(v[8], v[9], v[10], v[11]);
                o[3] = make_float4(v[12], v[13], v[14], v[15]);
            }
        } else {
            // fused 64->2 classifier: partial dot per quarter, reduce over 4 lanes
            float p0 = 0.0f, p1 = 0.0f;
#pragma unroll
            for (int j = 0; j < 16; j++) {
                int f = q * 16 + j;
                p0 = fmaf(v[j], sWc[2 * f + 0], p0);
                p1 = fmaf(v[j], sWc[2 * f + 1], p1);
            }
            p0 += __shfl_xor_sync(0xffffffffu, p0, 1);
            p1 += __shfl_xor_sync(0xffffffffu, p1, 1);
            p0 += __shfl_xor_sync(0xffffffffu, p0, 2);
            p1 += __shfl_xor_sync(0xffffffffu, p1, 2);
            if (q == 0 && node < N) {
                out[(size_t)node * 2 + 0] = p0 + bc[0];
                out[(size_t)node * 2 + 1] = p1 + bc[1];
            }
        }
    }
}

// ---------------------------------------------------------------------------
extern "C" void kernel_launch(void* const* d_in, const int* in_sizes, int n_in,
                              void* d_out, int out_size) {
    const float* x  = (const float*)d_in[0];
    const int*   src = (const int*)d_in[1];
    const int*   dst = (const int*)d_in[2];
    const float* W1 = (const float*)d_in[3];
    const float* b1 = (const float*)d_in[4];
    const float* W2 = (const float*)d_in[5];
    const float* b2 = (const float*)d_in[6];
    const float* Wc = (const float*)d_in[7];
    const float* bc = (const float*)d_in[8];
    float* out = (float*)d_out;

    int N = in_sizes[0] / D;
    int E = in_sizes[1];

    void *p_deg_out, *p_deg_in, *p_agg, *p_h1;
    cudaGetSymbolAddress(&p_deg_out, g_deg_out);
    cudaGetSymbolAddress(&p_deg_in,  g_deg_in);
    cudaGetSymbolAddress(&p_agg,     g_agg);
    cudaGetSymbolAddress(&p_h1,      g_h1);

    size_t smem_bytes = (D * D + 128 * XPAD + D * 2) * sizeof(float);  // ~50.5KB
    static bool attr_set = false;
    if (!attr_set) {
        cudaFuncSetAttribute(k_gemm<false>, cudaFuncAttributeMaxDynamicSharedMemorySize,
                             (int)smem_bytes);
        cudaFuncSetAttribute(k_gemm<true>, cudaFuncAttributeMaxDynamicSharedMemorySize,
                             (int)smem_bytes);
        attr_set = true;
    }

    // degrees
    cudaMemsetAsync(p_deg_out, 0, (size_t)N * sizeof(float), 0);
    cudaMemsetAsync(p_deg_in,  0, (size_t)N * sizeof(float), 0);
    k_deg<<<(E + 255) / 256, 256>>>(src, dst, E);
    k_isqrt<<<(N + 255) / 256, 256>>>(N);

    int sblk = (E * 16 + 255) / 256;
    int gblk = (N + 127) / 128;

    // layer 1
    cudaMemsetAsync(p_agg, 0, (size_t)N * D * sizeof(float), 0);
    k_scatter<<<sblk, 256>>>(x, src, dst, E);
    k_gemm<false><<<gblk, 128, smem_bytes>>>((const float*)p_agg, W1, b1, nullptr, nullptr,
                                             (float*)p_h1, N);

    // layer 2 + fused classifier
    cudaMemsetAsync(p_agg, 0, (size_t)N * D * sizeof(float), 0);
    k_scatter<<<sblk, 256>>>((const float*)p_h1, src, dst, E);
    k_gemm<true><<<gblk, 128, smem_bytes>>>((const float*)p_agg, W2, b2, Wc, bc, out, N);
}

// round 4
// speedup vs baseline: 2.1026x; 1.3723x over previous
#include <cuda_runtime.h>

#define D 64
#define NMAX 100000
#define EMAX 1000000
#define XPAD 65

// Scratch (allocation-free rule: __device__ globals)
__device__ int   g_cnt_out[NMAX];
__device__ int   g_cnt_in[NMAX];
__device__ float g_isq_out[NMAX];
__device__ float g_isq_in[NMAX];
__device__ int   g_row_off[NMAX + 1];
__device__ int   g_fill[NMAX];
__device__ int   g_csr_src[EMAX];
__device__ float g_h1[(size_t)NMAX * D];
__device__ int   g_part[1024];            // block partial sums for scan

// ---------------------------------------------------------------------------
// packed f32x2 helpers (Blackwell FFMA2 — only reachable via PTX)
// ---------------------------------------------------------------------------
__device__ __forceinline__ unsigned long long pack2(float lo, float hi) {
    unsigned long long r;
    asm("mov.b64 %0, {%1, %2};" : "=l"(r) : "f"(lo), "f"(hi));
    return r;
}
__device__ __forceinline__ void unpack2(unsigned long long v, float& lo, float& hi) {
    asm("mov.b64 {%0, %1}, %2;" : "=f"(lo), "=f"(hi) : "l"(v));
}
__device__ __forceinline__ unsigned long long fma2(unsigned long long a,
                                                   unsigned long long b,
                                                   unsigned long long c) {
    unsigned long long d;
    asm("fma.rn.f32x2 %0, %1, %2, %3;" : "=l"(d) : "l"(a), "l"(b), "l"(c));
    return d;
}

// ---------------------------------------------------------------------------
// Degree counting (int)
// ---------------------------------------------------------------------------
__global__ void k_deg(const int* __restrict__ src, const int* __restrict__ dst, int E) {
    int e = blockIdx.x * blockDim.x + threadIdx.x;
    if (e < E) {
        atomicAdd(&g_cnt_out[src[e]], 1);
        atomicAdd(&g_cnt_in[dst[e]], 1);
    }
}

// scan step 1: per-block sums of in-degree
__global__ void k_scan1(int N) {
    __shared__ int s[256];
    int t = threadIdx.x;
    int n = blockIdx.x * 256 + t;
    s[t] = (n < N) ? g_cnt_in[n] : 0;
    __syncthreads();
#pragma unroll
    for (int off = 128; off > 0; off >>= 1) {
        if (t < off) s[t] += s[t + off];
        __syncthreads();
    }
    if (t == 0) g_part[blockIdx.x] = s[0];
}

// scan step 2: exclusive scan of up to 512 block sums (single block)
__global__ void k_scan2(int NB) {
    __shared__ int s[512];
    int t = threadIdx.x;
    s[t] = (t < NB) ? g_part[t] : 0;
    __syncthreads();
    for (int off = 1; off < 512; off <<= 1) {
        int v = (t >= off) ? s[t - off] : 0;
        __syncthreads();
        s[t] += v;
        __syncthreads();
    }
    if (t < NB) g_part[t] = (t == 0) ? 0 : s[t - 1];
}

// scan step 3: row offsets, fill=0, isqrt degrees
__global__ void k_scan3(int N, int E) {
    __shared__ int s[256];
    int t = threadIdx.x;
    int n = blockIdx.x * 256 + t;
    int c = (n < N) ? g_cnt_in[n] : 0;
    s[t] = c;
    __syncthreads();
    for (int off = 1; off < 256; off <<= 1) {
        int v = (t >= off) ? s[t - off] : 0;
        __syncthreads();
        s[t] += v;
        __syncthreads();
    }
    if (n < N) {
        int excl = s[t] - c + g_part[blockIdx.x];
        g_row_off[n] = excl;
        g_fill[n] = 0;
        g_isq_in[n]  = rsqrtf((float)max(c, 1));
        g_isq_out[n] = rsqrtf((float)max(g_cnt_out[n], 1));
    }
    if (n == 0) g_row_off[N] = E;
}

// place edges: csr_src grouped by dst
__global__ void k_place(const int* __restrict__ src, const int* __restrict__ dst, int E) {
    int e = blockIdx.x * blockDim.x + threadIdx.x;
    if (e < E) {
        int d = dst[e];
        int pos = g_row_off[d] + atomicAdd(&g_fill[d], 1);
        g_csr_src[pos] = src[e];
    }
}

// ---------------------------------------------------------------------------
// Fused aggregate + GEMM (+ optional classifier).
// 256 threads, 128 nodes/block.
// Phase 1 (aggregate): warp w owns 16 nodes; lane l accumulates cols 2l,2l+1
//   of sum_{u->n} x_u * isq_out[u], then * isq_in[n], into smem X tile.
// Phase 2 (GEMM): warp w -> col quarter q=w&3 (W loads warp-uniform =
//   broadcast), node half = w>>2; thread = 2 adjacent nodes x 16 cols,
//   packed f32x2 FMAs. FUSE adds the 64->2 classifier via smem reduction.
// ---------------------------------------------------------------------------
template <bool FUSE>
__global__ __launch_bounds__(256, 3) void k_fused(
        const float* __restrict__ xin,
        const float* __restrict__ W,
        const float* __restrict__ b,
        const float* __restrict__ Wc,
        const float* __restrict__ bc,
        float* __restrict__ out, int N) {
    extern __shared__ float smem[];
    float* sW   = smem;                     // 4096
    float* sX   = sW + D * D;               // 128 * XPAD
    float* sCls = sX + 128 * XPAD;          // 128 * 8
    float* sWc  = sCls + 128 * 8;           // 128

    int tid = threadIdx.x;
    int w = tid >> 5;
    int lane = tid & 31;
    int nb = blockIdx.x * 128;

    for (int i = tid; i < D * D; i += 256) sW[i] = W[i];
    if (FUSE && tid < D * 2) sWc[tid] = Wc[tid];

    // ---- Phase 1: aggregation into sX ----
    const int* __restrict__ csr = g_csr_src;
#pragma unroll 1
    for (int nn = 0; nn < 16; nn++) {
        int local = w * 16 + nn;
        int n = nb + local;
        float ax = 0.0f, ay = 0.0f;
        if (n < N) {
            int beg = g_row_off[n];
            int end = g_row_off[n + 1];
            int e = beg;
            for (; e + 3 < end; e += 4) {
                int s0 = csr[e], s1 = csr[e + 1], s2 = csr[e + 2], s3 = csr[e + 3];
                float2 v0 = *reinterpret_cast<const float2*>(xin + (size_t)s0 * D + 2 * lane);
                float2 v1 = *reinterpret_cast<const float2*>(xin + (size_t)s1 * D + 2 * lane);
                float2 v2 = *reinterpret_cast<const float2*>(xin + (size_t)s2 * D + 2 * lane);
                float2 v3 = *reinterpret_cast<const float2*>(xin + (size_t)s3 * D + 2 * lane);
                float c0 = g_isq_out[s0], c1 = g_isq_out[s1];
                float c2 = g_isq_out[s2], c3 = g_isq_out[s3];
                ax = fmaf(c0, v0.x, ax); ay = fmaf(c0, v0.y, ay);
                ax = fmaf(c1, v1.x, ax); ay = fmaf(c1, v1.y, ay);
                ax = fmaf(c2, v2.x, ax); ay = fmaf(c2, v2.y, ay);
                ax = fmaf(c3, v3.x, ax); ay = fmaf(c3, v3.y, ay);
            }
            for (; e < end; e++) {
                int s0 = csr[e];
                float2 v0 = *reinterpret_cast<const float2*>(xin + (size_t)s0 * D + 2 * lane);
                float c0 = g_isq_out[s0];
                ax = fmaf(c0, v0.x, ax); ay = fmaf(c0, v0.y, ay);
            }
            float si = g_isq_in[n];
            ax *= si; ay *= si;
        }
        sX[local * XPAD + 2 * lane]     = ax;
        sX[local * XPAD + 2 * lane + 1] = ay;
    }
    __syncthreads();

    // ---- Phase 2: GEMM ----
    int q = w & 3;                 // column quarter (warp-uniform)
    int half = w >> 2;             // node half
    int n0 = half * 64 + 2 * lane; // local node (even); thread does n0, n0+1

    unsigned long long acc[2][8];
    {
        unsigned long long binit[8];
#pragma unroll
        for (int j = 0; j < 8; j++)
            binit[j] = pack2(b[q * 16 + 2 * j], b[q * 16 + 2 * j + 1]);
#pragma unroll
        for (int j = 0; j < 8; j++) { acc[0][j] = binit[j]; acc[1][j] = binit[j]; }
    }

    unsigned wbase = (unsigned)__cvta_generic_to_shared(&sW[q * 16]);
    unsigned xbase0 = (unsigned)__cvta_generic_to_shared(&sX[n0 * XPAD]);
    unsigned xbase1 = xbase0 + XPAD * 4;

#pragma unroll 8
    for (int k = 0; k < D; k++) {
        unsigned long long w2[8];
        unsigned waddr = wbase + k * (D * 4);
        asm("ld.shared.v2.u64 {%0,%1}, [%2];" : "=l"(w2[0]), "=l"(w2[1]) : "r"(waddr));
        asm("ld.shared.v2.u64 {%0,%1}, [%2];" : "=l"(w2[2]), "=l"(w2[3]) : "r"(waddr + 16));
        asm("ld.shared.v2.u64 {%0,%1}, [%2];" : "=l"(w2[4]), "=l"(w2[5]) : "r"(waddr + 32));
        asm("ld.shared.v2.u64 {%0,%1}, [%2];" : "=l"(w2[6]), "=l"(w2[7]) : "r"(waddr + 48));
        float a0, a1;
        asm("ld.shared.f32 %0, [%1];" : "=f"(a0) : "r"(xbase0 + k * 4));
        asm("ld.shared.f32 %0, [%1];" : "=f"(a1) : "r"(xbase1 + k * 4));
        unsigned long long a0p = pack2(a0, a0);
        unsigned long long a1p = pack2(a1, a1);
#pragma unroll
        for (int j = 0; j < 8; j++) {
            acc[0][j] = fma2(a0p, w2[j], acc[0][j]);
            acc[1][j] = fma2(a1p, w2[j], acc[1][j]);
        }
    }

#pragma unroll
    for (int m = 0; m < 2; m++) {
        int local = n0 + m;
        int node = nb + local;
        float v[16];
#pragma unroll
        for (int j = 0; j < 8; j++) unpack2(acc[m][j], v[2 * j], v[2 * j + 1]);
#pragma unroll
        for (int j = 0; j < 16; j++) v[j] = v[j] > 0.0f ? v[j] : 0.01f * v[j];

        if (!FUSE) {
            if (node < N) {
                float4* o = reinterpret_cast<float4*>(out + (size_t)node * D + q * 16);
                o[0] = make_float4(v[0], v[1], v[2], v[3]);
                o[1] = make_float4(v[4], v[5], v[6], v[7]);
                o[2] = make_float4(v[8], v[9], v[10], v[11]);
                o[3] = make_float4(v[12], v[13], v[14], v[15]);
            }
        } else {
            float p0 = 0.0f, p1 = 0.0f;
#pragma unroll
            for (int j = 0; j < 16; j++) {
                int f = q * 16 + j;
                p0 = fmaf(v[j], sWc[2 * f + 0], p0);
                p1 = fmaf(v[j], sWc[2 * f + 1], p1);
            }
            sCls[local * 8 + q * 2 + 0] = p0;
            sCls[local * 8 + q * 2 + 1] = p1;
        }
    }

    if (FUSE) {
        __syncthreads();
        // 256 threads -> 128 nodes x 2 outputs
        int local = tid >> 1;
        int o = tid & 1;
        int node = nb + local;
        if (node < N) {
            float p = sCls[local * 8 + 0 * 2 + o] + sCls[local * 8 + 1 * 2 + o]
                    + sCls[local * 8 + 2 * 2 + o] + sCls[local * 8 + 3 * 2 + o];
            out[(size_t)node * 2 + o] = p + bc[o];
        }
    }
}

// ---------------------------------------------------------------------------
extern "C" void kernel_launch(void* const* d_in, const int* in_sizes, int n_in,
                              void* d_out, int out_size) {
    const float* x  = (const float*)d_in[0];
    const int*   src = (const int*)d_in[1];
    const int*   dst = (const int*)d_in[2];
    const float* W1 = (const float*)d_in[3];
    const float* b1 = (const float*)d_in[4];
    const float* W2 = (const float*)d_in[5];
    const float* b2 = (const float*)d_in[6];
    const float* Wc = (const float*)d_in[7];
    const float* bc = (const float*)d_in[8];
    float* out = (float*)d_out;

    int N = in_sizes[0] / D;
    int E = in_sizes[1];

    void *p_cnt_out, *p_cnt_in, *p_h1;
    cudaGetSymbolAddress(&p_cnt_out, g_cnt_out);
    cudaGetSymbolAddress(&p_cnt_in,  g_cnt_in);
    cudaGetSymbolAddress(&p_h1,      g_h1);

    size_t smem_bytes = (D * D + 128 * XPAD + 128 * 8 + 128) * sizeof(float);
    static bool attr_set = false;
    if (!attr_set) {
        cudaFuncSetAttribute(k_fused<false>, cudaFuncAttributeMaxDynamicSharedMemorySize,
                             (int)smem_bytes);
        cudaFuncSetAttribute(k_fused<true>, cudaFuncAttributeMaxDynamicSharedMemorySize,
                             (int)smem_bytes);
        attr_set = true;
    }

    int NB = (N + 255) / 256;   // scan blocks (<= 512)

    // CSR build + degree scales
    cudaMemsetAsync(p_cnt_out, 0, (size_t)N * sizeof(int), 0);
    cudaMemsetAsync(p_cnt_in,  0, (size_t)N * sizeof(int), 0);
    k_deg<<<(E + 255) / 256, 256>>>(src, dst, E);
    k_scan1<<<NB, 256>>>(N);
    k_scan2<<<1, 512>>>(NB);
    k_scan3<<<NB, 256>>>(N, E);
    k_place<<<(E + 255) / 256, 256>>>(src, dst, E);

    int gblk = (N + 127) / 128;

    // layer 1: x -> h1
    k_fused<false><<<gblk, 256, smem_bytes>>>(x, W1, b1, nullptr, nullptr,
                                              (float*)p_h1, N);
    // layer 2 + classifier: h1 -> out
    k_fused<true><<<gblk, 256, smem_bytes>>>((const float*)p_h1, W2, b2, Wc, bc, out, N);
}